// round 12
// baseline (speedup 1.0000x reference)
#include <cuda_runtime.h>

// Fixed problem structure (M=512 checks, N=1024 vars, SHIFTS=(0,7,101)):
//   E = 3072 edges, check degree 6, var degree 3.
//   edges sorted by (check,var) => check c owns edges [6c, 6c+6).
#define ITERS 5
#define MCHK  512
#define NVAR  1024
#define NEDGE 3072

#define LOG2E 1.4426950408889634f
#define LN2   0.6931471805599453f

// g_fast: 1 iff w_iter==1 && llr_iter==1 && w_final==1 && llr_final==1
// everywhere (verified by prepack; only 0 is ever written -> race-free).
__device__ int    g_fast = 1;
__device__ float4 g_wlt [ITERS * NEDGE];  // general path: {w0, w1, llr_iter*log2e, 0}
__device__ int2   g_sib [NEDGE];          // {sib0_b8 | sib1_b8<<16, ev} (float2-slot byte offsets)
__device__ float2 g_fw  [NEDGE];          // {bitcast(fidx_b8), w_final*ln2}

__global__ void prepack_kernel(const float* __restrict__ w_iter,
                               const float* __restrict__ llr_iter,
                               const int*   __restrict__ vs_idx,
                               const int*   __restrict__ edge_var,
                               const int*   __restrict__ fin_idx,
                               const float* __restrict__ w_final,
                               const float* __restrict__ llr_final)
{
    const int c = threadIdx.x;
    const int t = blockIdx.x;
    bool ok = true;
#pragma unroll
    for (int j = 0; j < 6; ++j) {
        const int e  = 6 * c + j;
        const float w0 = w_iter[t * 2 * NEDGE + 2 * e];
        const float w1 = w_iter[t * 2 * NEDGE + 2 * e + 1];
        const float li = llr_iter[t * NVAR + edge_var[e]];
        ok = ok && (w0 == 1.0f) && (w1 == 1.0f) && (li == 1.0f);
        g_wlt[t * NEDGE + j * MCHK + c] = make_float4(w0, w1, li * LOG2E, 0.0f);
    }
    if (t == 0) {
#pragma unroll
        for (int j = 0; j < 6; ++j) {
            const int e  = 6 * c + j;
            const int s0 = vs_idx[2 * e];
            const int s1 = vs_idx[2 * e + 1];
            // byte offsets into a float2-per-slot message array (slot*8 < 2^15)
            const int b0 = ((s0 % 6) * MCHK + s0 / 6) * 8;
            const int b1 = ((s1 % 6) * MCHK + s1 / 6) * 8;
            g_sib[j * MCHK + c] = make_int2(b0 | (b1 << 16), edge_var[e]);
        }
#pragma unroll
        for (int k = 0; k < 2; ++k) {
            const int v = c + MCHK * k;
            ok = ok && (llr_final[v] == 1.0f);
#pragma unroll
            for (int p = 0; p < 3; ++p) {
                const int q = 3 * v + p;
                const int e = fin_idx[q];
                const float wf = w_final[q];
                ok = ok && (wf == 1.0f);
                float2 fw;
                fw.x = __int_as_float(((e % 6) * MCHK + e / 6) * 8);
                fw.y = wf * LN2;
                g_fw[(k * 3 + p) * MCHK + c] = fw;
            }
        }
    }
    if (!ok) g_fast = 0;
}

// Exclusive products (pair-tree, depth 3), 0.9995 damping folded in:
// m[j] = 0.9995 * prod_{k != j} v[k]
__device__ __forceinline__ void excl_prod(const float v[6], float m[6])
{
    const float p01  = v[0] * v[1];
    const float p23  = v[2] * v[3];
    const float p45s = (0.9995f * v[4]) * v[5];
    const float B = p23 * p45s;            // excl {0,1}, scaled
    const float C = p01 * p45s;            // excl {2,3}, scaled
    const float D = 0.9995f * (p01 * p23); // excl {4,5}, scaled
    m[0] = v[1] * B;  m[1] = v[0] * B;
    m[2] = v[3] * C;  m[3] = v[2] * C;
    m[4] = v[5] * D;  m[5] = v[4] * D;
}

// General-path check update in log2 domain.
__device__ __forceinline__ void check_update_log(const float x_in[6], float c2v[6])
{
    float n[6], d[6];
#pragma unroll
    for (int j = 0; j < 6; ++j) {
        const float x  = fminf(fmaxf(x_in[j], -25.0f), 25.0f);
        const float ea = exp2f(x);
        n[j] = ea - 1.0f;
        d[j] = ea + 1.0f;
    }
    float sn[6], sd[6];
    sn[5] = 1.0f; sd[5] = 1.0f;
#pragma unroll
    for (int j = 4; j >= 0; --j) {
        sn[j] = sn[j + 1] * n[j + 1];
        sd[j] = sd[j + 1] * d[j + 1];
    }
    float pn = 0.9995f, pd = 1.0f;
#pragma unroll
    for (int j = 0; j < 6; ++j) {
        const float P = pn * sn[j];
        const float Q = pd * sd[j];
        c2v[j] = __log2f(Q + P) - __log2f(Q - P);
        pn *= n[j];
        pd *= d[j];
    }
}

__device__ __forceinline__ float tanh_half(float x)  // tanh(x/2), NaN-safe
{
    const float e = __expf(x);
    return 1.0f - __fdividef(2.0f, e + 1.0f);
}

// Two batch items per block, messages stored as float2 {item0, item1} per
// edge slot: every smem op (STS.64 / LDS.64), address unpack, barrier, and
// index load is amortized over both items.
__global__ __launch_bounds__(512, 2)
void bp_decode_kernel(const float* __restrict__ llr,        // [B, N]
                      const float* __restrict__ llr_final,  // [N]
                      float*       __restrict__ out,        // [B, N]
                      int B)
{
    __shared__ float2 sm[2][NEDGE];     // double-buffered pair messages (48 KB)

    const int c  = threadIdx.x;
    const int b0 = 2 * blockIdx.x;
    const int has2 = (b0 + 1 < B);
    const float* __restrict__ llr0 = llr + (size_t)b0 * NVAR;
    const float* __restrict__ llr1 = llr + (size_t)(b0 + has2) * NVAR;

    unsigned int sibpk[6];              // packed {sb0_b8 | sb1_b8<<16}
    float pl0[6], pl1[6];               // tanh(llr/2) per item
#pragma unroll
    for (int j = 0; j < 6; ++j) {
        const int2 s = g_sib[j * MCHK + c];          // 1 LDG.64 per j
        sibpk[j] = (unsigned int)s.x;
        pl0[j] = tanh_half(__ldg(&llr0[s.y]));
        pl1[j] = tanh_half(__ldg(&llr1[s.y]));
    }

    int cur = 0;
    if (g_fast) {
        // ======= fast path: unit weights -> tanh-domain loop, no logs =======
        float m0[6], m1[6];
        excl_prod(pl0, m0);                          // peeled iteration 0
        excl_prod(pl1, m1);

#pragma unroll
        for (int t = 1; t < ITERS; ++t) {
            const char* smc = (const char*)sm[cur];
#pragma unroll
            for (int j = 0; j < 6; ++j)
                sm[cur][j * MCHK + c] = make_float2(m0[j], m1[j]);  // STS.64
            __syncthreads();

            float v0[6], v1[6];
#pragma unroll
            for (int j = 0; j < 6; ++j) {
                const float2 A = *(const float2*)(smc + (sibpk[j] & 0xFFFFu));
                const float2 Bv = *(const float2*)(smc + (sibpk[j] >> 16));
                {   // item 0
                    const float s1_ = A.x + Bv.x;
                    const float d1_ = fmaf(A.x, Bv.x, 1.0f);
                    const float nu  = fmaf(pl0[j], d1_, s1_);
                    const float de  = fmaf(pl0[j], s1_, d1_);  // > 0
                    v0[j] = __fdividef(nu, de);
                }
                {   // item 1
                    const float s1_ = A.y + Bv.y;
                    const float d1_ = fmaf(A.y, Bv.y, 1.0f);
                    const float nu  = fmaf(pl1[j], d1_, s1_);
                    const float de  = fmaf(pl1[j], s1_, d1_);
                    v1[j] = __fdividef(nu, de);
                }
            }
            excl_prod(v0, m0);
            excl_prod(v1, m1);
            cur ^= 1;
        }

        // log-free epilogue (valid because w_final==1 && llr_final==1):
        //   sigmoid(sum_p 2*atanh(m_p) + llr) = 1/(1 + e^{-llr} * prod (1-m)/(1+m))
#pragma unroll
        for (int j = 0; j < 6; ++j)
            sm[cur][j * MCHK + c] = make_float2(m0[j], m1[j]);
        __syncthreads();

        const char* smc = (const char*)sm[cur];
        float* __restrict__ out0 = out + (size_t)b0 * NVAR;
        float* __restrict__ out1 = out + (size_t)(b0 + has2) * NVAR;
#pragma unroll
        for (int k = 0; k < 2; ++k) {
            const int v = c + MCHK * k;
            float2 mp[3];
#pragma unroll
            for (int p = 0; p < 3; ++p) {
                const float2 fw = g_fw[(k * 3 + p) * MCHK + c];
                mp[p] = *(const float2*)(smc + __float_as_int(fw.x));
            }
            const float n0 = (1.0f - mp[0].x) * (1.0f - mp[1].x) * (1.0f - mp[2].x);
            const float d0 = (1.0f + mp[0].x) * (1.0f + mp[1].x) * (1.0f + mp[2].x);
            const float n1 = (1.0f - mp[0].y) * (1.0f - mp[1].y) * (1.0f - mp[2].y);
            const float d1 = (1.0f + mp[0].y) * (1.0f + mp[1].y) * (1.0f + mp[2].y);
            const float t0 = __expf(-__ldg(&llr0[v])) * __fdividef(n0, d0);
            const float t1 = __expf(-__ldg(&llr1[v])) * __fdividef(n1, d1);
            out0[v] = __fdividef(1.0f, 1.0f + t0);
            if (has2) out1[v] = __fdividef(1.0f, 1.0f + t1);
        }
    } else {
        // ======= general path: arbitrary weights, log2-domain pair messages ===
        float lv0[6], lv1[6];
#pragma unroll
        for (int j = 0; j < 6; ++j) {
            const int ev = g_sib[j * MCHK + c].y;
            lv0[j] = __ldg(&llr0[ev]);
            lv1[j] = __ldg(&llr1[ev]);
        }

        float c0[6], c1[6], x0[6], x1[6];
        {
            const float4* __restrict__ wlt = g_wlt;  // t=0, messages zero
#pragma unroll
            for (int j = 0; j < 6; ++j) {
                const float wz = wlt[j * MCHK + c].z;
                x0[j] = lv0[j] * wz;
                x1[j] = lv1[j] * wz;
            }
            check_update_log(x0, c0);
            check_update_log(x1, c1);
        }
#pragma unroll
        for (int t = 1; t < ITERS; ++t) {
            const float4* __restrict__ wlt = g_wlt + t * NEDGE;
            const char* smc = (const char*)sm[cur];
#pragma unroll
            for (int j = 0; j < 6; ++j)
                sm[cur][j * MCHK + c] = make_float2(c0[j], c1[j]);
            __syncthreads();
#pragma unroll
            for (int j = 0; j < 6; ++j) {
                const float4 w  = wlt[j * MCHK + c];
                const float2 A  = *(const float2*)(smc + (sibpk[j] & 0xFFFFu));
                const float2 Bv = *(const float2*)(smc + (sibpk[j] >> 16));
                x0[j] = A.x * w.x + Bv.x * w.y + lv0[j] * w.z;
                x1[j] = A.y * w.x + Bv.y * w.y + lv1[j] * w.z;
            }
            check_update_log(x0, c0);
            check_update_log(x1, c1);
            cur ^= 1;
        }

#pragma unroll
        for (int j = 0; j < 6; ++j)
            sm[cur][j * MCHK + c] = make_float2(c0[j], c1[j]);
        __syncthreads();

        const char* smc = (const char*)sm[cur];
        float* __restrict__ out0 = out + (size_t)b0 * NVAR;
        float* __restrict__ out1 = out + (size_t)(b0 + has2) * NVAR;
#pragma unroll
        for (int k = 0; k < 2; ++k) {
            const int v = c + MCHK * k;
            float mg0 = 0.0f, mg1 = 0.0f;
#pragma unroll
            for (int p = 0; p < 3; ++p) {
                const float2 fw = g_fw[(k * 3 + p) * MCHK + c];
                const float2 mm = *(const float2*)(smc + __float_as_int(fw.x));
                mg0 += mm.x * fw.y;                  // fw.y prescaled *ln2
                mg1 += mm.y * fw.y;
            }
            const float lf = llr_final[v];
            mg0 += __ldg(&llr0[v]) * lf;
            mg1 += __ldg(&llr1[v]) * lf;
            out0[v] = __fdividef(1.0f, 1.0f + __expf(-mg0));
            if (has2) out1[v] = __fdividef(1.0f, 1.0f + __expf(-mg1));
        }
    }
}

extern "C" void kernel_launch(void* const* d_in, const int* in_sizes, int n_in,
                              void* d_out, int out_size)
{
    // metadata order: llr, w_iter, llr_iter, w_final, llr_final,
    //                 v_sum_idx, seg_vsum, c_prod_idx, seg_cprod,
    //                 final_idx, seg_final, edge_var
    const float* llr       = (const float*)d_in[0];
    const float* w_iter    = (const float*)d_in[1];
    const float* llr_iter  = (const float*)d_in[2];
    const float* w_final   = (const float*)d_in[3];
    const float* llr_final = (const float*)d_in[4];
    const int*   vs_idx    = (const int*)  d_in[5];
    const int*   fin_idx   = (const int*)  d_in[9];
    const int*   edge_var  = (const int*)  d_in[11];
    float*       out       = (float*)d_out;

    const int B = in_sizes[0] / NVAR;

    prepack_kernel<<<ITERS, MCHK>>>(w_iter, llr_iter, vs_idx, edge_var,
                                    fin_idx, w_final, llr_final);
    bp_decode_kernel<<<(B + 1) / 2, MCHK>>>(llr, llr_final, out, B);
}